// round 1
// baseline (speedup 1.0000x reference)
#include <cuda_runtime.h>
#include <math.h>

// Problem constants
#define LL   512
#define DS   256
#define HH   32
#define DP   128
#define KRBF 36
#define KTOT 68   // 32 (gate) + 36 (rbf)

// Scratch (no allocations allowed)
__device__ float g_t[LL * HH * DP];     // t = left @ Wg  : (512, 32, 128)  (8 MB)
__device__ float g_left[LL * HH];       // (512, 32)
__device__ float g_right_t[HH * LL];    // transposed right: (32, 512)
__device__ float g_cas[LL * 4];         // C-alpha coords, padded

typedef unsigned long long ull;

__device__ __forceinline__ void fma2(ull &d, ull a, ull b) {
    asm("fma.rn.f32x2 %0, %1, %2, %0;" : "+l"(d) : "l"(a), "l"(b));
}
__device__ __forceinline__ ull dup2(float x) {
    ull r; asm("mov.b64 %0, {%1, %1};" : "=l"(r) : "f"(x)); return r;
}
__device__ __forceinline__ void unpk(ull v, float &lo, float &hi) {
    asm("mov.b64 {%0, %1}, %2;" : "=f"(lo), "=f"(hi) : "l"(v));
}

// ---------------------------------------------------------------------------
// Kernel 1: LayerNorm + left/right projections + cas extraction
// grid = 512 (one block per residue l), 256 threads
// ---------------------------------------------------------------------------
__global__ __launch_bounds__(256) void k_prep(
    const float* __restrict__ xyz, const float* __restrict__ state,
    const float* __restrict__ ln_w, const float* __restrict__ ln_b,
    const float* __restrict__ w_left, const float* __restrict__ b_left,
    const float* __restrict__ w_right, const float* __restrict__ b_right)
{
    int l = blockIdx.x;
    int tid = threadIdx.x;
    __shared__ float st_s[DS];
    __shared__ float red[18];

    float x = state[l * DS + tid];
    float s = x, q = x * x;
    #pragma unroll
    for (int o = 16; o; o >>= 1) {
        s += __shfl_xor_sync(0xFFFFFFFFu, s, o);
        q += __shfl_xor_sync(0xFFFFFFFFu, q, o);
    }
    int wid = tid >> 5, lane = tid & 31;
    if (lane == 0) { red[wid] = s; red[8 + wid] = q; }
    __syncthreads();
    if (tid == 0) {
        float S = 0.f, Q = 0.f;
        #pragma unroll
        for (int i = 0; i < 8; i++) { S += red[i]; Q += red[8 + i]; }
        float mu = S * (1.0f / DS);
        float var = Q * (1.0f / DS) - mu * mu;
        red[16] = mu;
        red[17] = rsqrtf(var + 1e-5f);
    }
    __syncthreads();
    float mu = red[16], inv = red[17];
    st_s[tid] = (x - mu) * inv * ln_w[tid] + ln_b[tid];
    __syncthreads();

    if (tid < 64) {
        int j = tid & 31;
        bool isL = tid < 32;
        const float* w = isL ? w_left : w_right;
        float acc = isL ? b_left[j] : b_right[j];
        #pragma unroll 8
        for (int i = 0; i < DS; i++) acc += st_s[i] * w[i * HH + j];
        if (isL) g_left[l * HH + j] = acc;
        else     g_right_t[j * LL + l] = acc;
    }
    if (tid < 3) g_cas[l * 4 + tid] = xyz[l * 9 + 3 + tid];
}

// ---------------------------------------------------------------------------
// Kernel 2: t[l,j,p] = sum_i left[l,i] * w_gate[(i*32+j)*128 + p]
// grid = (64 l-groups of 8, 4 j-groups of 8), 128 threads (p)
// ---------------------------------------------------------------------------
__global__ __launch_bounds__(128) void k_t(const float* __restrict__ w_gate)
{
    int lb = blockIdx.x * 8;
    int jb = blockIdx.y * 8;
    int p = threadIdx.x;
    __shared__ float ls[8 * HH];
    for (int idx = threadIdx.x; idx < 8 * HH; idx += 128)
        ls[idx] = g_left[lb * HH + idx];
    __syncthreads();

    for (int j = jb; j < jb + 8; j++) {
        float acc[8];
        #pragma unroll
        for (int lt = 0; lt < 8; lt++) acc[lt] = 0.f;
        #pragma unroll
        for (int i = 0; i < HH; i++) {
            float wv = w_gate[(i * HH + j) * DP + p];
            #pragma unroll
            for (int lt = 0; lt < 8; lt++) acc[lt] += ls[lt * HH + i] * wv;
        }
        #pragma unroll
        for (int lt = 0; lt < 8; lt++)
            g_t[(lb + lt) * (HH * DP) + j * DP + p] = acc[lt];
    }
}

// ---------------------------------------------------------------------------
// Kernel 3 (main): fused RBF + logits GEMM + sigmoid * feat
// grid = (512 l, 2 m-halves), 256 threads
// Each block: l fixed, 256 m's (4 passes of 64), all 128 p.
// Thread tile: 8 m x 4 p, two accumulator sets (logits, feat), f32x2 packed.
// ---------------------------------------------------------------------------
__global__ __launch_bounds__(256) void k_main(
    const float* __restrict__ w_rbf, const float* __restrict__ b_rbf,
    const float* __restrict__ b_gate, float* __restrict__ out)
{
    extern __shared__ float sm[];
    float* Bs = sm;                       // [68][128]
    float* As = Bs + KTOT * DP;           // [68][64]
    float* dist_s = As + KTOT * 64;       // [64]

    int l = blockIdx.x;
    int mhalf = blockIdx.y;
    int tid = threadIdx.x;
    int tc = tid & 31;        // p-column group (4 p each)
    int tr = tid >> 5;        // m-row group (8 m each)
    int p0 = tc * 4;

    // Stage B = [t_l (32x128) ; w_rbf (36x128)] once per block
    for (int idx = tid; idx < KTOT * DP; idx += 256) {
        int row = idx >> 7, p = idx & 127;
        Bs[idx] = (row < HH) ? g_t[l * (HH * DP) + row * DP + p]
                             : w_rbf[(row - HH) * DP + p];
    }

    float clx = g_cas[l * 4], cly = g_cas[l * 4 + 1], clz = g_cas[l * 4 + 2];
    float4 bg = *(const float4*)(b_gate + p0);
    float4 br = *(const float4*)(b_rbf + p0);

    const float MU0 = 2.0f;
    const float DMU = 20.0f / 35.0f;           // linspace(2,22,36) step
    const float INV_SIG = 36.0f / 20.0f;       // 1/sigma

    for (int pass = 0; pass < 4; pass++) {
        int mb = mhalf * 256 + pass * 64;
        __syncthreads();  // Bs/As ready-for-reuse barrier

        // Stage A rows 0..31: right^T, coalesced
        for (int idx = tid; idx < HH * 64; idx += 256) {
            int k = idx >> 6, m = idx & 63;
            As[k * 64 + m] = g_right_t[k * LL + mb + m];
        }
        // distances for this m-chunk
        if (tid < 64) {
            int m = mb + tid;
            float dx = g_cas[m * 4]     - clx;
            float dy = g_cas[m * 4 + 1] - cly;
            float dz = g_cas[m * 4 + 2] - clz;
            float d2 = dx * dx + dy * dy + dz * dz;
            dist_s[tid] = sqrtf(fmaxf(d2, 1e-12f));
        }
        __syncthreads();
        // Stage A rows 32..67: RBF features
        for (int idx = tid; idx < KRBF * 64; idx += 256) {
            int kr = idx >> 6, m = idx & 63;
            float u = (dist_s[m] - (MU0 + (float)kr * DMU)) * INV_SIG;
            As[(HH + kr) * 64 + m] = __expf(-u * u);
        }
        __syncthreads();

        // Register-tiled GEMM: 8m x 4p, packed f32x2 along p
        ull accL[8][2], accF[8][2];
        #pragma unroll
        for (int mi = 0; mi < 8; mi++) {
            accL[mi][0] = 0ull; accL[mi][1] = 0ull;
            accF[mi][0] = 0ull; accF[mi][1] = 0ull;
        }
        const float* Arow = As + tr * 8;

        #pragma unroll 8
        for (int k = 0; k < HH; k++) {
            ulonglong2 b = *(const ulonglong2*)(Bs + k * DP + p0);
            const float* ar = Arow + k * 64;
            float4 a0 = *(const float4*)(ar);
            float4 a1 = *(const float4*)(ar + 4);
            float a[8] = {a0.x, a0.y, a0.z, a0.w, a1.x, a1.y, a1.z, a1.w};
            #pragma unroll
            for (int mi = 0; mi < 8; mi++) {
                ull ad = dup2(a[mi]);
                fma2(accL[mi][0], ad, b.x);
                fma2(accL[mi][1], ad, b.y);
            }
        }
        #pragma unroll 9
        for (int k = HH; k < KTOT; k++) {
            ulonglong2 b = *(const ulonglong2*)(Bs + k * DP + p0);
            const float* ar = Arow + k * 64;
            float4 a0 = *(const float4*)(ar);
            float4 a1 = *(const float4*)(ar + 4);
            float a[8] = {a0.x, a0.y, a0.z, a0.w, a1.x, a1.y, a1.z, a1.w};
            #pragma unroll
            for (int mi = 0; mi < 8; mi++) {
                ull ad = dup2(a[mi]);
                fma2(accF[mi][0], ad, b.x);
                fma2(accF[mi][1], ad, b.y);
            }
        }

        // Epilogue: sigmoid(logits + b_gate) * (feat + b_rbf)
        #pragma unroll
        for (int mi = 0; mi < 8; mi++) {
            float lg0, lg1, lg2, lg3, f0, f1, f2, f3;
            unpk(accL[mi][0], lg0, lg1); unpk(accL[mi][1], lg2, lg3);
            unpk(accF[mi][0], f0, f1);   unpk(accF[mi][1], f2, f3);
            lg0 += bg.x; lg1 += bg.y; lg2 += bg.z; lg3 += bg.w;
            f0  += br.x; f1  += br.y; f2  += br.z; f3  += br.w;
            float4 o;
            o.x = f0 * __fdividef(1.0f, 1.0f + __expf(-lg0));
            o.y = f1 * __fdividef(1.0f, 1.0f + __expf(-lg1));
            o.z = f2 * __fdividef(1.0f, 1.0f + __expf(-lg2));
            o.w = f3 * __fdividef(1.0f, 1.0f + __expf(-lg3));
            int m = mb + tr * 8 + mi;
            *(float4*)(out + ((size_t)l * LL + m) * DP + p0) = o;
        }
    }
}

// ---------------------------------------------------------------------------
extern "C" void kernel_launch(void* const* d_in, const int* in_sizes, int n_in,
                              void* d_out, int out_size)
{
    const float* xyz     = (const float*)d_in[0];
    const float* state   = (const float*)d_in[1];
    const float* ln_w    = (const float*)d_in[2];
    const float* ln_b    = (const float*)d_in[3];
    const float* w_rbf   = (const float*)d_in[4];
    const float* b_rbf   = (const float*)d_in[5];
    const float* w_left  = (const float*)d_in[6];
    const float* b_left  = (const float*)d_in[7];
    const float* w_right = (const float*)d_in[8];
    const float* b_right = (const float*)d_in[9];
    const float* w_gate  = (const float*)d_in[10];
    const float* b_gate  = (const float*)d_in[11];
    float* out = (float*)d_out;

    k_prep<<<LL, 256>>>(xyz, state, ln_w, ln_b, w_left, b_left, w_right, b_right);
    k_t<<<dim3(64, 4), 128>>>(w_gate);

    int smem = (KTOT * DP + KTOT * 64 + 64) * (int)sizeof(float);  // 52480 B
    cudaFuncSetAttribute(k_main, cudaFuncAttributeMaxDynamicSharedMemorySize, smem);
    k_main<<<dim3(LL, 2), 256, smem>>>(w_rbf, b_rbf, b_gate, out);
}